// round 3
// baseline (speedup 1.0000x reference)
#include <cuda_runtime.h>
#include <cuda_bf16.h>
#include <cstdint>
#include <math_constants.h>

#define NN 256          // NUM_NEURONS
#define NS 512          // NUM_SAMPLES
#define MAXSP 32        // MAX_SPIKES (rounds)
#define NSTEPS 32       // RK4 steps per round
#define V_RESET 1.0f
#define NPL 8           // neurons per lane (256 / 32)

__device__ __forceinline__ float fast_sigmoid(float v) {
    return 1.0f / (1.0f + __expf(-v));
}

__device__ __forceinline__ void drift(float v, float i, float ic, float mu1, float mu2,
                                      float& dv, float& di, float& ds) {
    dv = mu1 * (i + ic - v);
    di = -mu2 * i;
    ds = fast_sigmoid(v);
}

__device__ __forceinline__ void rk4_step(float v, float i, float s,
                                         float ic, float mu1, float mu2, float h,
                                         float& vn, float& in_, float& sn) {
    float dv1, di1, ds1, dv2, di2, ds2, dv3, di3, ds3, dv4, di4, ds4;
    drift(v, i, ic, mu1, mu2, dv1, di1, ds1);
    float v2 = v + 0.5f * h * dv1;
    float i2 = i + 0.5f * h * di1;
    drift(v2, i2, ic, mu1, mu2, dv2, di2, ds2);
    float v3 = v + 0.5f * h * dv2;
    float i3 = i + 0.5f * h * di2;
    drift(v3, i3, ic, mu1, mu2, dv3, di3, ds3);
    float v4 = v + h * dv3;
    float i4 = i + h * di3;
    drift(v4, i4, ic, mu1, mu2, dv4, di4, ds4);
    float c = h * (1.0f / 6.0f);
    vn  = v + c * (dv1 + 2.0f * dv2 + 2.0f * dv3 + dv4);
    in_ = i + c * (di1 + 2.0f * di2 + 2.0f * di3 + di4);
    sn  = s + c * (ds1 + 2.0f * ds2 + 2.0f * ds3 + ds4);
}

#define LOAD8(dst, ptr) do {                                   \
    float4 _x0 = ((const float4*)(ptr))[0];                    \
    float4 _x1 = ((const float4*)(ptr))[1];                    \
    (dst)[0]=_x0.x; (dst)[1]=_x0.y; (dst)[2]=_x0.z; (dst)[3]=_x0.w; \
    (dst)[4]=_x1.x; (dst)[5]=_x1.y; (dst)[6]=_x1.z; (dst)[7]=_x1.w; \
} while(0)

__global__ __launch_bounds__(32, 16)
void snn_warp_kernel(const float* __restrict__ ic_g,     // [NN]
                     const float* __restrict__ w,        // [NN, NN]
                     const float* __restrict__ mu_g,     // [2]
                     const float* __restrict__ v0_g,     // [NN]
                     const float* __restrict__ i0_g,     // [NN]
                     const float* __restrict__ s0_g,     // [NS, NN]
                     const float* __restrict__ reset_s,  // [MAXSP, NS, NN]
                     const int*   __restrict__ t1_p,     // scalar
                     float* __restrict__ out_times,      // [NS, MAXSP]
                     float* __restrict__ out_vals,       // [NS, MAXSP, NN, 3]
                     float* __restrict__ out_marks)      // [NS, MAXSP, NN]
{
    const int smp  = blockIdx.x;
    const int lane = threadIdx.x;     // 0..31
    const int base = lane * NPL;      // first neuron owned by this lane

    const float t1f = (float)(*t1_p);
    const float mu1 = mu_g[0];
    const float mu2 = mu_g[1];

    float icr[NPL], v[NPL], ii[NPL], s[NPL];
    LOAD8(icr, ic_g + base);
    LOAD8(v,   v0_g + base);
    LOAD8(ii,  i0_g + base);
    LOAD8(s,   s0_g + (size_t)smp * NN + base);

    float t0 = 0.0f;

    #pragma unroll 1
    for (int k = 0; k < MAXSP; k++) {
        // prefetch reset row for this round (latency hidden behind step loop)
        float rs[NPL];
        LOAD8(rs, reset_s + ((size_t)k * NS + smp) * NN + base);

        const float dt = (t1f - t0) * (1.0f / NSTEPS);
        bool done = false;
        float tev = t1f;
        bool em[NPL];
        #pragma unroll
        for (int j = 0; j < NPL; j++) em[j] = false;

        if (dt > 0.0f) {
            float t = t0;
            #pragma unroll 1
            for (int st = 0; st < NSTEPS; st++) {
                float vn[NPL], in_[NPL], sn[NPL];
                #pragma unroll
                for (int j = 0; j < NPL; j++)
                    rk4_step(v[j], ii[j], s[j], icr[j], mu1, mu2, dt,
                             vn[j], in_[j], sn[j]);

                // fast path: just the max (no index, no payload)
                float m = sn[0];
                #pragma unroll
                for (int j = 1; j < NPL; j++) m = fmaxf(m, sn[j]);
                #pragma unroll
                for (int off = 16; off; off >>= 1)
                    m = fmaxf(m, __shfl_xor_sync(0xffffffffu, m, off));

                if (m > 0.0f) {
                    // slow path (rare): full argmax with s_prev payload,
                    // tie -> lowest neuron index (matches jnp.argmax)
                    float bv = -CUDART_INF_F; int bi = 0; float bsp = 0.0f;
                    #pragma unroll
                    for (int j = 0; j < NPL; j++)
                        if (sn[j] > bv) { bv = sn[j]; bi = base + j; bsp = s[j]; }
                    #pragma unroll
                    for (int off = 16; off; off >>= 1) {
                        float ov  = __shfl_xor_sync(0xffffffffu, bv, off);
                        int   oi  = __shfl_xor_sync(0xffffffffu, bi, off);
                        float osp = __shfl_xor_sync(0xffffffffu, bsp, off);
                        if (ov > bv || (ov == bv && oi < bi)) { bv = ov; bi = oi; bsp = osp; }
                    }
                    float frac = bsp / (bsp - bv + 1e-12f);
                    frac = fminf(fmaxf(frac, 0.0f), 1.0f);
                    tev = t + frac * dt;
                    #pragma unroll
                    for (int j = 0; j < NPL; j++) {
                        em[j] = sn[j] > 0.0f;
                        v[j]  += frac * (vn[j] - v[j]);
                        ii[j] += frac * (in_[j] - ii[j]);
                        s[j]  += frac * (sn[j] - s[j]);
                    }
                    done = true;
                    break;
                }
                #pragma unroll
                for (int j = 0; j < NPL; j++) { v[j] = vn[j]; ii[j] = in_[j]; s[j] = sn[j]; }
                t += dt;
            }
        }
        // yev == current (v, ii, s); tev set above (t1f if no trigger)

        // ---- outputs for this round (pre-reset values) ----
        const size_t ob = ((size_t)smp * MAXSP + k) * NN + base;

        float vb[24];
        #pragma unroll
        for (int j = 0; j < NPL; j++) {
            vb[3*j]   = v[j];
            vb[3*j+1] = ii[j];
            vb[3*j+2] = s[j];
        }
        float4* vo = (float4*)(out_vals + ob * 3);
        #pragma unroll
        for (int q = 0; q < 6; q++)
            vo[q] = make_float4(vb[4*q], vb[4*q+1], vb[4*q+2], vb[4*q+3]);

        float4* mo = (float4*)(out_marks + ob);
        mo[0] = make_float4(em[0]?1.f:0.f, em[1]?1.f:0.f, em[2]?1.f:0.f, em[3]?1.f:0.f);
        mo[1] = make_float4(em[4]?1.f:0.f, em[5]?1.f:0.f, em[6]?1.f:0.f, em[7]?1.f:0.f);

        if (lane == 0) out_times[smp * MAXSP + k] = tev;

        // ---- eidx = first neuron with emask (argmax over bools) ----
        int li = 0x7fffffff;
        #pragma unroll
        for (int j = NPL - 1; j >= 0; j--) if (em[j]) li = base + j;
        #pragma unroll
        for (int off = 16; off; off >>= 1)
            li = min(li, __shfl_xor_sync(0xffffffffu, li, off));
        const int eidx = (li == 0x7fffffff) ? 0 : li;

        // ---- reset & carry to next round ----
        float wr[NPL];
        if (done) {
            LOAD8(wr, w + (size_t)eidx * NN + base);
        } else {
            #pragma unroll
            for (int j = 0; j < NPL; j++) wr[j] = 0.0f;
        }
        #pragma unroll
        for (int j = 0; j < NPL; j++) {
            v[j]  -= em[j] ? V_RESET : 0.0f;
            ii[j] += wr[j];
            s[j]   = fminf(em[j] ? rs[j] : s[j], 0.0f);
        }
        t0 = tev;
    }
}

extern "C" void kernel_launch(void* const* d_in, const int* in_sizes, int n_in,
                              void* d_out, int out_size) {
    const float* ic      = (const float*)d_in[0];
    const float* w       = (const float*)d_in[1];
    const float* mu      = (const float*)d_in[2];
    const float* v0      = (const float*)d_in[3];
    const float* i0      = (const float*)d_in[4];
    const float* s0      = (const float*)d_in[5];
    const float* reset_s = (const float*)d_in[6];
    const int*   t1      = (const int*)d_in[7];

    float* out = (float*)d_out;
    float* out_times = out;                                    // NS*MAXSP
    float* out_vals  = out + (size_t)NS * MAXSP;               // NS*MAXSP*NN*3
    float* out_marks = out_vals + (size_t)NS * MAXSP * NN * 3; // NS*MAXSP*NN

    snn_warp_kernel<<<NS, 32>>>(ic, w, mu, v0, i0, s0, reset_s, t1,
                                out_times, out_vals, out_marks);
}

// round 4
// speedup vs baseline: 2.5291x; 2.5291x over previous
#include <cuda_runtime.h>
#include <cuda_bf16.h>
#include <cstdint>
#include <math_constants.h>

#define NN 256          // NUM_NEURONS
#define NS 512          // NUM_SAMPLES
#define MAXSP 32        // MAX_SPIKES (rounds)
#define NSTEPS 32       // RK4 steps per round
#define V_RESET 1.0f

__device__ __forceinline__ float fast_sigmoid(float v) {
    return 1.0f / (1.0f + __expf(-v));
}

// Linear RK4 propagation for (v, i) with drift dv = mu1*(i + c - v), di = -mu2*i.
// Returns stage v's (sigmoid inputs) and the final (vn, in).
__device__ __forceinline__ void lin_rk4(float v, float i, float c,
                                        float h, float mu1, float mu2,
                                        float& v2, float& v3, float& v4,
                                        float& vn, float& in_) {
    float k1v = mu1 * (i + c - v);
    float k1i = -mu2 * i;
    float v2_ = v + 0.5f * h * k1v;
    float i2  = i + 0.5f * h * k1i;
    float k2v = mu1 * (i2 + c - v2_);
    float k2i = -mu2 * i2;
    float v3_ = v + 0.5f * h * k2v;
    float i3  = i + 0.5f * h * k2i;
    float k3v = mu1 * (i3 + c - v3_);
    float k3i = -mu2 * i3;
    float v4_ = v + h * k3v;
    float i4  = i + h * k3i;
    float k4v = mu1 * (i4 + c - v4_);
    float k4i = -mu2 * i4;
    float c6 = h * (1.0f / 6.0f);
    vn  = v + c6 * (k1v + 2.0f * k2v + 2.0f * k3v + k4v);
    in_ = i + c6 * (k1i + 2.0f * k2i + 2.0f * k3i + k4i);
    v2 = v2_; v3 = v3_; v4 = v4_;
}

__global__ __launch_bounds__(NN, 8)
void snn_kernel(const float* __restrict__ ic_g,     // [NN]
                const float* __restrict__ w,        // [NN, NN]
                const float* __restrict__ mu_g,     // [2]
                const float* __restrict__ v0_g,     // [NN]
                const float* __restrict__ i0_g,     // [NN]
                const float* __restrict__ s0_g,     // [NS, NN]
                const float* __restrict__ reset_s,  // [MAXSP, NS, NN]
                const int*   __restrict__ t1_p,     // scalar
                float* __restrict__ out_times,      // [NS, MAXSP]
                float* __restrict__ out_vals,       // [NS, MAXSP, NN, 3]
                float* __restrict__ out_marks)      // [NS, MAXSP, NN]
{
    const int smp = blockIdx.x;
    const int n   = threadIdx.x;
    const int warp = n >> 5, lane = n & 31;

    const float t1f = (float)(*t1_p);
    const float mu1 = mu_g[0];
    const float mu2 = mu_g[1];
    const float ic  = ic_g[n];

    float v = v0_g[n];
    float i = i0_g[n];
    float s = s0_g[(size_t)smp * NN + n];
    float t0 = 0.0f;

    __shared__ float red_val[8];
    __shared__ int   red_idx[8];
    __shared__ float red_sp[8];
    __shared__ unsigned ballots[8];

    #pragma unroll 1
    for (int k = 0; k < MAXSP; k++) {
        // prefetch reset value for this round
        const float rs = reset_s[((size_t)k * NS + smp) * NN + n];

        const float dt = (t1f - t0) * (1.0f / NSTEPS);
        bool  done = false;
        float tev  = t1f;
        bool  em   = false;
        int   eidx = 0;

        if (dt > 0.0f) {
            // ---- precompute linear RK4 coefficients for this round ----
            // columns of the affine map: (v, i, ic) -> (v2, v3, v4, vn, in)
            float A2, A3, A4, An, dum0;
            float B2, B3, B4, Bn, Pn;
            float C2, C3, C4, Cn, dum1;
            lin_rk4(1.f, 0.f, 0.f, dt, mu1, mu2, A2, A3, A4, An, dum0);
            lin_rk4(0.f, 1.f, 0.f, dt, mu1, mu2, B2, B3, B4, Bn, Pn);
            lin_rk4(0.f, 0.f, 1.f, dt, mu1, mu2, C2, C3, C4, Cn, dum1);
            const float c2 = C2 * ic, c3 = C3 * ic, c4 = C4 * ic, cn = Cn * ic;
            const float c6 = dt * (1.0f / 6.0f);

            float t = t0;
            #pragma unroll 1
            for (int st = 0; st < NSTEPS; st++) {
                const float v2 = fmaf(A2, v, fmaf(B2, i, c2));
                const float v3 = fmaf(A3, v, fmaf(B3, i, c3));
                const float v4 = fmaf(A4, v, fmaf(B4, i, c4));
                const float vn = fmaf(An, v, fmaf(Bn, i, cn));
                const float in_ = Pn * i;
                const float ds = fast_sigmoid(v)
                               + 2.0f * (fast_sigmoid(v2) + fast_sigmoid(v3))
                               + fast_sigmoid(v4);
                const float sn = fmaf(c6, ds, s);

                // one BAR.RED per step: did ANY neuron cross?
                if (__syncthreads_or(sn > 0.0f)) {
                    // ---- rare trigger path: full argmax (tie -> lowest idx) ----
                    float bv = sn; int bi = n; float bsp = s;
                    #pragma unroll
                    for (int off = 16; off; off >>= 1) {
                        float ov  = __shfl_xor_sync(0xffffffffu, bv, off);
                        int   oi  = __shfl_xor_sync(0xffffffffu, bi, off);
                        float osp = __shfl_xor_sync(0xffffffffu, bsp, off);
                        if (ov > bv || (ov == bv && oi < bi)) { bv = ov; bi = oi; bsp = osp; }
                    }
                    if (lane == 0) { red_val[warp] = bv; red_idx[warp] = bi; red_sp[warp] = bsp; }
                    __syncthreads();
                    float mval = red_val[0]; int midx = red_idx[0]; float msp = red_sp[0];
                    #pragma unroll
                    for (int wv = 1; wv < 8; wv++) {
                        float ov = red_val[wv]; int oi = red_idx[wv];
                        if (ov > mval || (ov == mval && oi < midx)) {
                            mval = ov; midx = oi; msp = red_sp[wv];
                        }
                    }
                    float frac = msp / (msp - mval + 1e-12f);
                    frac = fminf(fmaxf(frac, 0.0f), 1.0f);
                    tev = t + frac * dt;
                    em  = sn > 0.0f;
                    v += frac * (vn - v);
                    i += frac * (in_ - i);
                    s += frac * (sn - s);
                    done = true;

                    // eidx = first neuron with emask set
                    unsigned b = __ballot_sync(0xffffffffu, em);
                    if (lane == 0) ballots[warp] = b;
                    __syncthreads();
                    #pragma unroll
                    for (int wv = 0; wv < 8; wv++) {
                        unsigned bb = ballots[wv];
                        if (bb) { eidx = wv * 32 + (__ffs(bb) - 1); break; }
                    }
                    break;
                }
                v = vn; i = in_; s = sn;
                t += dt;
            }
        }
        // outputs (pre-reset event state); tev = t1f if no trigger
        const size_t base = ((size_t)smp * MAXSP + k) * NN + n;
        if (n == 0) out_times[smp * MAXSP + k] = tev;
        out_vals[base * 3 + 0] = v;
        out_vals[base * 3 + 1] = i;
        out_vals[base * 3 + 2] = s;
        out_marks[base] = em ? 1.0f : 0.0f;

        // reset & carry
        const float wr = done ? w[(size_t)eidx * NN + n] : 0.0f;
        v -= em ? V_RESET : 0.0f;
        i += wr;
        s  = fminf(em ? rs : s, 0.0f);
        t0 = tev;
    }
}

extern "C" void kernel_launch(void* const* d_in, const int* in_sizes, int n_in,
                              void* d_out, int out_size) {
    const float* ic      = (const float*)d_in[0];
    const float* w       = (const float*)d_in[1];
    const float* mu      = (const float*)d_in[2];
    const float* v0      = (const float*)d_in[3];
    const float* i0      = (const float*)d_in[4];
    const float* s0      = (const float*)d_in[5];
    const float* reset_s = (const float*)d_in[6];
    const int*   t1      = (const int*)d_in[7];

    float* out = (float*)d_out;
    float* out_times = out;                                    // NS*MAXSP
    float* out_vals  = out + (size_t)NS * MAXSP;               // NS*MAXSP*NN*3
    float* out_marks = out_vals + (size_t)NS * MAXSP * NN * 3; // NS*MAXSP*NN

    snn_kernel<<<NS, NN>>>(ic, w, mu, v0, i0, s0, reset_s, t1,
                           out_times, out_vals, out_marks);
}